// round 11
// baseline (speedup 1.0000x reference)
#include <cuda_runtime.h>
#include <cstdint>

#define BATCH  8
#define NCH    64
#define TLEN   16384
#define KW     127
#define NF     512
#define NH     386            // NF - KW + 1 valid outputs per segment
#define NSEG   43             // ceil(TLEN / NH)
#define NBINS  257
#define BS_TOT (BATCH * NSEG) // 344

__device__ __align__(16) float2 g_Xs[(size_t)NBINS * BS_TOT * NCH]; // [f][bs][i]
__device__ __align__(16) float2 g_Ws[(size_t)NBINS * NCH * NCH];    // [f][i][o]
__device__ __align__(16) float2 g_Ys[(size_t)NBINS * BS_TOT * NCH]; // [f][bs][o]

__device__ __forceinline__ float2 cmul(float2 a, float2 b) {
    return make_float2(a.x * b.x - a.y * b.y, a.x * b.y + a.y * b.x);
}

// 4 interleaved radix-2 Stockham FFT-512 (natural order in/out). Result in B.
// Caller must __syncthreads() after filling A. tw[m] = exp(sign*2*pi*i*m/512).
__device__ __forceinline__ void fft512x4(float2 (*A)[NF], float2 (*B)[NF],
                                         const float2* tw, int tid) {
    float2 (*S)[NF] = A; float2 (*D)[NF] = B;
    #pragma unroll
    for (int st = 0; st < 9; st++) {
        const int Ns = 1 << st, mask = Ns - 1;
        const float2 w = tw[(tid & mask) << (8 - st)];
        const int idx = ((tid >> st) << (st + 1)) | (tid & mask);
        #pragma unroll
        for (int u = 0; u < 4; u++) {
            float2 v0 = S[u][tid], v1 = cmul(S[u][tid + 256], w);
            D[u][idx]      = make_float2(v0.x + v1.x, v0.y + v1.y);
            D[u][idx + Ns] = make_float2(v0.x - v1.x, v0.y - v1.y);
        }
        __syncthreads();
        float2 (*t)[NF] = S; S = D; D = t;
    }
}
__device__ __forceinline__ void build_tw(float2* tw, int tid, float sgn) {
    float a = sgn * (6.28318530717958647692f / NF) * (float)tid;
    float s, c; sincosf(a, &s, &c);
    tw[tid] = make_float2(c, s);
}

// ---- W spectra: blocks (i, pg); 4 FFTs over o-pairs ----
__global__ void __launch_bounds__(256) fft_w(const float* __restrict__ W) {
    __shared__ float2 A[4][NF], B[4][NF], tw[256];
    const int tid = threadIdx.x;
    const int i = blockIdx.x >> 3, pg = blockIdx.x & 7;
    build_tw(tw, tid, -1.f);
    #pragma unroll
    for (int u = 0; u < 4; u++) {
        const int o0 = ((pg << 2) + u) << 1;
        for (int n = tid; n < NF; n += 256) {
            float re = (n < KW) ? W[((size_t)o0 * NCH + i) * KW + n] : 0.f;
            float im = (n < KW) ? W[((size_t)(o0 + 1) * NCH + i) * KW + n] : 0.f;
            A[u][n] = make_float2(re, im);
        }
    }
    __syncthreads();
    fft512x4(A, B, tw, tid);
    #pragma unroll
    for (int u = 0; u < 4; u++) {
        const int o0 = ((pg << 2) + u) << 1;
        for (int f = tid; f < NBINS; f += 256) {
            float2 zf = B[u][f], zc = B[u][(NF - f) & (NF - 1)];
            g_Ws[((size_t)f * NCH + i) * NCH + o0] =
                make_float2(0.5f * (zf.x + zc.x), 0.5f * (zf.y - zc.y));
            g_Ws[((size_t)f * NCH + i) * NCH + o0 + 1] =
                make_float2(0.5f * (zf.y + zc.y), 0.5f * (zc.x - zf.x));
        }
    }
}

// ---- x spectra: blocks (b, s, pg); 4 FFTs over cin-pairs ----
__global__ void __launch_bounds__(256) fft_x(const float* __restrict__ x) {
    __shared__ float2 A[4][NF], B[4][NF], tw[256];
    const int tid = threadIdx.x;
    const int b = blockIdx.x / 344, r2 = blockIdx.x % 344;
    const int s = r2 >> 3, pg = r2 & 7;
    build_tw(tw, tid, -1.f);
    #pragma unroll
    for (int u = 0; u < 4; u++) {
        const int i0 = ((pg << 2) + u) << 1;
        const int tbase = s * NH - 63;
        for (int n = tid; n < NF; n += 256) {
            const int t = tbase + n;
            const bool ok = (t >= 0) && (t < TLEN);
            float re = ok ? x[((size_t)b * NCH + i0) * TLEN + t] : 0.f;
            float im = ok ? x[((size_t)b * NCH + i0 + 1) * TLEN + t] : 0.f;
            A[u][n] = make_float2(re, im);
        }
    }
    __syncthreads();
    fft512x4(A, B, tw, tid);
    const int bs = b * NSEG + s;
    #pragma unroll
    for (int u = 0; u < 4; u++) {
        const int i0 = ((pg << 2) + u) << 1;
        for (int f = tid; f < NBINS; f += 256) {
            float2 zf = B[u][f], zc = B[u][(NF - f) & (NF - 1)];
            g_Xs[((size_t)f * BS_TOT + bs) * NCH + i0] =
                make_float2(0.5f * (zf.x + zc.x), 0.5f * (zf.y - zc.y));
            g_Xs[((size_t)f * BS_TOT + bs) * NCH + i0 + 1] =
                make_float2(0.5f * (zf.y + zc.y), 0.5f * (zc.x - zf.x));
        }
    }
}

// ---- per-bin complex GEMM: Y[f][bs][o] = sum_i X[f][bs][i] * W[f][i][o] ----
#define CG_SMEM (64 * 64 * 8 + 32 * 66 * 8)   // 49664
__global__ void __launch_bounds__(256) cgemm_k() {
    extern __shared__ float2 dsm[];
    float2* sW = dsm;                                    // [64][64]
    float2 (*sX)[66] = (float2(*)[66])(dsm + 4096);      // [32][66] padded
    const int tid = threadIdx.x;
    const int f = blockIdx.x, bs0 = blockIdx.y << 5;
    {   // load W bin (float4 bulk) and X tile
        const float4* s4 = (const float4*)(g_Ws + (size_t)f * NCH * NCH);
        float4* d4 = (float4*)sW;
        #pragma unroll
        for (int e = tid; e < 2048; e += 256) d4[e] = s4[e];
        for (int e = tid; e < 2048; e += 256) {
            const int r = e >> 6, i = e & 63, bs = bs0 + r;
            sX[r][i] = (bs < BS_TOT)
                     ? g_Xs[((size_t)f * BS_TOT + bs) * NCH + i]
                     : make_float2(0.f, 0.f);
        }
    }
    __syncthreads();
    const int r = tid >> 3, c = tid & 7;
    float ar[8], ai[8];
    #pragma unroll
    for (int oo = 0; oo < 8; oo++) { ar[oo] = 0.f; ai[oo] = 0.f; }
    #pragma unroll 4
    for (int i = 0; i < NCH; i++) {
        const float2 xa = sX[r][i];
        #pragma unroll
        for (int oo = 0; oo < 8; oo++) {
            const float2 w = sW[i * 64 + c + (oo << 3)];
            ar[oo] += xa.x * w.x - xa.y * w.y;
            ai[oo] += xa.x * w.y + xa.y * w.x;
        }
    }
    const int bs = bs0 + r;
    if (bs < BS_TOT) {
        #pragma unroll
        for (int oo = 0; oo < 8; oo++)
            g_Ys[((size_t)f * BS_TOT + bs) * NCH + c + (oo << 3)] =
                make_float2(ar[oo], ai[oo]);
    }
}

// ---- inverse FFT + centered crop: blocks (b, s, pg); 4 iFFTs over o-pairs ----
__global__ void __launch_bounds__(256) ifft_y(float* __restrict__ y) {
    __shared__ float2 A[4][NF], B[4][NF], tw[256];
    const int tid = threadIdx.x;
    const int b = blockIdx.x / 344, r2 = blockIdx.x % 344;
    const int s = r2 >> 3, pg = r2 & 7;
    build_tw(tw, tid, 1.f);
    const int bs = b * NSEG + s;
    #pragma unroll
    for (int u = 0; u < 4; u++) {
        const int o0 = ((pg << 2) + u) << 1;
        for (int f = tid; f < NBINS; f += 256) {
            const float4 yy = *(const float4*)
                &g_Ys[((size_t)f * BS_TOT + bs) * NCH + o0];  // y0=(x,y) y1=(z,w)
            A[u][f] = make_float2(yy.x - yy.w, yy.y + yy.z);  // y0 + i*y1
            if (f >= 1 && f < 256)                             // conj mirror
                A[u][NF - f] = make_float2(yy.x + yy.w, yy.z - yy.y);
        }
    }
    __syncthreads();
    fft512x4(A, B, tw, tid);
    const float sc = 1.f / NF;
    #pragma unroll
    for (int u = 0; u < 4; u++) {
        const int o0 = ((pg << 2) + u) << 1;
        for (int n = KW - 1 + tid; n < NF; n += 256) {   // n in [126, 512)
            const int t = s * NH + n - (KW - 1);
            if (t < TLEN) {
                y[((size_t)b * NCH + o0) * TLEN + t]     = B[u][n].x * sc;
                y[((size_t)b * NCH + o0 + 1) * TLEN + t] = B[u][n].y * sc;
            }
        }
    }
}

extern "C" void kernel_launch(void* const* d_in, const int* in_sizes, int n_in,
                              void* d_out, int out_size) {
    const float* x = (const float*)d_in[0];   // [B][CIN][T]
    const float* W = (const float*)d_in[1];   // [COUT][CIN][K]
    float* y       = (float*)d_out;           // [B][COUT][T]
    (void)in_sizes; (void)n_in; (void)out_size;
    cudaFuncSetAttribute(cgemm_k, cudaFuncAttributeMaxDynamicSharedMemorySize,
                         CG_SMEM);
    fft_w<<<512, 256>>>(W);                   // 2048 packed FFTs
    fft_x<<<BATCH * 344, 256>>>(x);           // 11008 packed FFTs
    cgemm_k<<<dim3(NBINS, 11), 256, CG_SMEM>>>();
    ifft_y<<<BATCH * 344, 256>>>(y);          // 11008 packed iFFTs
}

// round 12
// speedup vs baseline: 1.0677x; 1.0677x over previous
#include <cuda_runtime.h>
#include <cstdint>

#define BATCH  8
#define NCH    64
#define TLEN   16384
#define KW     127
#define NF     512
#define NH     386
#define NSEG   43
#define NBINS  257
#define BS_TOT 344

__device__ __align__(16) float2 g_Xs[(size_t)NBINS * BS_TOT * NCH]; // [f][bs][i]
__device__ __align__(16) float2 g_Ws[(size_t)NBINS * NCH * NCH];    // [f][i][o]
__device__ __align__(16) float2 g_Ys[(size_t)NBINS * BS_TOT * NCH]; // [f][bs][o]

#define PD(i) ((i) + ((i) >> 3))   // smem pad: stride 9 per 8 -> <=2-way conflicts
#define FSZ 576

__device__ __forceinline__ float2 cmul(float2 a, float2 b) {
    return make_float2(a.x*b.x - a.y*b.y, a.x*b.y + a.y*b.x);
}
__device__ __forceinline__ float2 cadd(float2 a, float2 b){ return make_float2(a.x+b.x, a.y+b.y); }
__device__ __forceinline__ float2 csub(float2 a, float2 b){ return make_float2(a.x-b.x, a.y-b.y); }

// Radix-8 Stockham FFT-512, 64 threads (j), natural in/out. Result in Db.
// tw[m] = exp(SG*2*pi*i*m/512). Contains block-wide syncthreads.
template<int SG>
__device__ __forceinline__ void fft512_r8(float2* Sb, float2* Db,
                                          const float2* tw, int j) {
    float2* S = Sb; float2* D = Db;
    #pragma unroll
    for (int st = 0; st < 3; st++) {
        const int Ns = (st == 0) ? 1 : (st == 1) ? 8 : 64;
        float2 v[8];
        #pragma unroll
        for (int p = 0; p < 8; p++) v[p] = S[PD(j + (p << 6))];
        if (st == 1) {
            const int m = (j & 7) << 3;
            #pragma unroll
            for (int p = 1; p < 8; p++) v[p] = cmul(v[p], tw[p * m]);
        } else if (st == 2) {
            #pragma unroll
            for (int p = 1; p < 8; p++) v[p] = cmul(v[p], tw[p * j]);
        }
        float2 u[8];
        {   // DFT-8, sign SG, natural order (2 radix-2 levels in registers)
            float2 A0=cadd(v[0],v[4]), A1=csub(v[0],v[4]);
            float2 B0=cadd(v[2],v[6]), B1=csub(v[2],v[6]);
            float2 C0=cadd(v[1],v[5]), C1=csub(v[1],v[5]);
            float2 D0=cadd(v[3],v[7]), D1=csub(v[3],v[7]);
            float2 iB1 = (SG > 0) ? make_float2(-B1.y, B1.x) : make_float2(B1.y, -B1.x);
            float2 iD1 = (SG > 0) ? make_float2(-D1.y, D1.x) : make_float2(D1.y, -D1.x);
            float2 E0=cadd(A0,B0), E2=csub(A0,B0), E1=cadd(A1,iB1), E3=csub(A1,iB1);
            float2 O0=cadd(C0,D0), O2=csub(C0,D0), O1=cadd(C1,iD1), O3=csub(C1,iD1);
            const float c = 0.70710678118654752440f;
            float2 T1 = (SG > 0) ? make_float2(c*(O1.x - O1.y), c*(O1.x + O1.y))
                                 : make_float2(c*(O1.x + O1.y), c*(O1.y - O1.x));
            float2 T2 = (SG > 0) ? make_float2(-O2.y, O2.x) : make_float2(O2.y, -O2.x);
            float2 T3 = (SG > 0) ? make_float2(-c*(O3.x + O3.y), c*(O3.x - O3.y))
                                 : make_float2(c*(O3.y - O3.x), -c*(O3.x + O3.y));
            u[0]=cadd(E0,O0); u[4]=csub(E0,O0);
            u[1]=cadd(E1,T1); u[5]=csub(E1,T1);
            u[2]=cadd(E2,T2); u[6]=csub(E2,T2);
            u[3]=cadd(E3,T3); u[7]=csub(E3,T3);
        }
        const int base = ((j / Ns) * (Ns << 3)) + (j % Ns);
        #pragma unroll
        for (int q = 0; q < 8; q++) D[PD(base + Ns * q)] = u[q];
        __syncthreads();
        float2* t = S; S = D; D = t;
    }
}
__device__ __forceinline__ void build_tw512(float2* tw, int tid, float sgn) {
    for (int m = tid; m < NF; m += 256) {
        float a = sgn * (6.28318530717958647692f / NF) * (float)m;
        float s, c; sincosf(a, &s, &c);
        tw[m] = make_float2(c, s);
    }
}

// ---- W spectra (scale 1/NF folded in): blocks (i, pg), 4 packed FFTs ----
__global__ void __launch_bounds__(256) fft_w(const float* __restrict__ W) {
    __shared__ float2 A[4][FSZ], Bb[4][FSZ], tw[NF];
    const int tid = threadIdx.x;
    const int i = blockIdx.x >> 3, pg = blockIdx.x & 7;
    const int u = tid >> 6, j = tid & 63;
    build_tw512(tw, tid, -1.f);
    const int o0 = ((pg << 2) + u) << 1;
    const float* wr = W + ((size_t)o0 * NCH + i) * KW;
    const float* wi = wr + (size_t)NCH * KW;
    #pragma unroll
    for (int p = 0; p < 8; p++) {
        const int n = j + (p << 6);
        const bool ok = n < KW;
        A[u][PD(n)] = make_float2(ok ? wr[n] : 0.f, ok ? wi[n] : 0.f);
    }
    __syncthreads();
    fft512_r8<-1>(A[u], Bb[u], tw, j);
    const float h = 0.5f / NF;
    for (int f = j; f < NBINS; f += 64) {
        float2 zf = Bb[u][PD(f)], zc = Bb[u][PD((NF - f) & (NF - 1))];
        float4 out;
        out.x = h*(zf.x + zc.x); out.y = h*(zf.y - zc.y);
        out.z = h*(zf.y + zc.y); out.w = h*(zc.x - zf.x);
        *(float4*)&g_Ws[((size_t)f * NCH + i) * NCH + o0] = out;
    }
}

// ---- x spectra: blocks (b, s, pg), 4 packed FFTs ----
__global__ void __launch_bounds__(256) fft_x(const float* __restrict__ x) {
    __shared__ float2 A[4][FSZ], Bb[4][FSZ], tw[NF];
    const int tid = threadIdx.x;
    const int b = blockIdx.x / 344, r2 = blockIdx.x % 344;
    const int s = r2 >> 3, pg = r2 & 7;
    const int u = tid >> 6, j = tid & 63;
    build_tw512(tw, tid, -1.f);
    const int i0 = ((pg << 2) + u) << 1;
    const int tbase = s * NH - 63;
    const float* xr = x + ((size_t)b * NCH + i0) * TLEN;
    const float* xi = xr + TLEN;
    #pragma unroll
    for (int p = 0; p < 8; p++) {
        const int n = j + (p << 6);
        const int t = tbase + n;
        const bool ok = (t >= 0) && (t < TLEN);
        A[u][PD(n)] = make_float2(ok ? xr[t] : 0.f, ok ? xi[t] : 0.f);
    }
    __syncthreads();
    fft512_r8<-1>(A[u], Bb[u], tw, j);
    const int bs = b * NSEG + s;
    for (int f = j; f < NBINS; f += 64) {
        float2 zf = Bb[u][PD(f)], zc = Bb[u][PD((NF - f) & (NF - 1))];
        float4 out;
        out.x = 0.5f*(zf.x + zc.x); out.y = 0.5f*(zf.y - zc.y);
        out.z = 0.5f*(zf.y + zc.y); out.w = 0.5f*(zc.x - zf.x);
        *(float4*)&g_Xs[((size_t)f * BS_TOT + bs) * NCH + i0] = out;
    }
}

// ---- per-bin cgemm, 4bs x 8o register tile: grid (257, 3), 256 thr ----
#define CG_SMEM ((64 * 64 + 128 * 65) * 8)   // 99328
__global__ void __launch_bounds__(256) cgemm_k() {
    extern __shared__ float2 dsm[];
    float2* sW = dsm;            // [64][64]
    float2* sX = dsm + 4096;     // [128][65] padded rows
    const int tid = threadIdx.x;
    const int f = blockIdx.x, bs0 = blockIdx.y << 7;
    {
        const float4* s4 = (const float4*)(g_Ws + (size_t)f * NCH * NCH);
        float4* d4 = (float4*)sW;
        #pragma unroll
        for (int e = tid; e < 2048; e += 256) d4[e] = s4[e];
    }
    for (int e = tid; e < 8192; e += 256) {
        const int r = e >> 6, i = e & 63, bs = bs0 + r;
        sX[r * 65 + i] = (bs < BS_TOT)
            ? g_Xs[((size_t)f * BS_TOT + bs) * NCH + i] : make_float2(0.f, 0.f);
    }
    __syncthreads();
    const int c8 = (tid & 7) << 3;       // 8 contiguous outputs
    const int r4 = (tid >> 3) << 2;      // 4 contiguous bs rows
    float ar[4][8], ai[4][8];
    #pragma unroll
    for (int m = 0; m < 4; m++)
        #pragma unroll
        for (int oo = 0; oo < 8; oo++) { ar[m][oo] = 0.f; ai[m][oo] = 0.f; }
    #pragma unroll 2
    for (int i = 0; i < NCH; i++) {
        float2 xa[4];
        #pragma unroll
        for (int m = 0; m < 4; m++) xa[m] = sX[(r4 + m) * 65 + i];
        #pragma unroll
        for (int oo = 0; oo < 8; oo++) {
            const float2 w = sW[(i << 6) + c8 + oo];
            #pragma unroll
            for (int m = 0; m < 4; m++) {
                ar[m][oo] += xa[m].x * w.x - xa[m].y * w.y;
                ai[m][oo] += xa[m].x * w.y + xa[m].y * w.x;
            }
        }
    }
    #pragma unroll
    for (int m = 0; m < 4; m++) {
        const int bs = bs0 + r4 + m;
        if (bs < BS_TOT) {
            float2* dst = g_Ys + ((size_t)f * BS_TOT + bs) * NCH + c8;
            #pragma unroll
            for (int oo = 0; oo < 8; oo += 2)
                *(float4*)&dst[oo] = make_float4(ar[m][oo], ai[m][oo],
                                                 ar[m][oo+1], ai[m][oo+1]);
        }
    }
}

// ---- inverse FFT + centered crop ----
__global__ void __launch_bounds__(256) ifft_y(float* __restrict__ y) {
    __shared__ float2 A[4][FSZ], Bb[4][FSZ], tw[NF];
    const int tid = threadIdx.x;
    const int b = blockIdx.x / 344, r2 = blockIdx.x % 344;
    const int s = r2 >> 3, pg = r2 & 7;
    const int u = tid >> 6, j = tid & 63;
    build_tw512(tw, tid, 1.f);
    const int bs = b * NSEG + s;
    const int o0 = ((pg << 2) + u) << 1;
    for (int f = j; f < NBINS; f += 64) {
        const float4 yy = *(const float4*)&g_Ys[((size_t)f * BS_TOT + bs) * NCH + o0];
        A[u][PD(f)] = make_float2(yy.x - yy.w, yy.y + yy.z);       // y0 + i*y1
        if (f >= 1 && f < 256)
            A[u][PD(NF - f)] = make_float2(yy.x + yy.w, yy.z - yy.y);
    }
    __syncthreads();
    fft512_r8<1>(A[u], Bb[u], tw, j);
    float* yr = y + ((size_t)b * NCH + o0) * TLEN;
    float* yi = yr + TLEN;
    #pragma unroll
    for (int p = 1; p < 8; p++) {
        const int n = j + (p << 6);
        if (n >= KW - 1) {
            const int t = s * NH + n - (KW - 1);
            if (t < TLEN) {
                const float2 v = Bb[u][PD(n)];   // 1/NF already folded into Ws
                yr[t] = v.x; yi[t] = v.y;
            }
        }
    }
}

extern "C" void kernel_launch(void* const* d_in, const int* in_sizes, int n_in,
                              void* d_out, int out_size) {
    const float* x = (const float*)d_in[0];
    const float* W = (const float*)d_in[1];
    float* y       = (float*)d_out;
    (void)in_sizes; (void)n_in; (void)out_size;
    cudaFuncSetAttribute(cgemm_k, cudaFuncAttributeMaxDynamicSharedMemorySize, CG_SMEM);
    fft_w<<<512, 256>>>(W);
    fft_x<<<BATCH * 344, 256>>>(x);
    cgemm_k<<<dim3(NBINS, 3), 256, CG_SMEM>>>();
    ifft_y<<<BATCH * 344, 256>>>(y);
}